// round 15
// baseline (speedup 1.0000x reference)
#include <cuda_runtime.h>
#include <cuda_bf16.h>
#include <cuda_fp16.h>
#include <math.h>
#include <stdint.h>

#define B_ 2
#define T_ 2048
#define D_ 1024
#define H_ 16
#define HD_ 64
#define QSCALE (0.125f * 1.4426950408889634f)   // 1/sqrt(64) * log2(e)
#define SOFTMAX_SHIFT 4.0f

// ---------------- scratch ----------------
__device__ uint32_t g_xf[2097152];                         // x fp16 single [4096,512]
__device__ uint32_t g_Wqf[1572864];                        // Wqkv fp16 single [3072,512]
__device__ uint32_t g_Wof[524288];                         // Wout fp16 single [1024,512]
__device__ uint32_t g_Qf[2097152];                         // [B,H,T,HD] fp16 single (scaled)
__device__ uint32_t g_Kf[2097152];                         // fp16 single
__device__ uint32_t g_Vf[2097152];                         // fp16 single
__device__ uint32_t g_Of[2097152];                         // [B,T,H*HD] fp16 single
__device__ float g_cosT[T_][32];
__device__ float g_sinT[T_][32];

// ================= helpers =================
__device__ __forceinline__ uint32_t smem_u32(const void* p) {
    uint32_t a;
    asm("{ .reg .u64 t; cvta.to.shared.u64 t, %1; cvt.u32.u64 %0, t; }" : "=r"(a) : "l"(p));
    return a;
}
__device__ __forceinline__ void ldsm_x4(uint32_t* r, uint32_t addr) {
    asm volatile("ldmatrix.sync.aligned.m8n8.x4.shared.b16 {%0,%1,%2,%3}, [%4];"
                 : "=r"(r[0]), "=r"(r[1]), "=r"(r[2]), "=r"(r[3]) : "r"(addr));
}
__device__ __forceinline__ void ldsm_x4_t(uint32_t* r, uint32_t addr) {
    asm volatile("ldmatrix.sync.aligned.m8n8.x4.trans.shared.b16 {%0,%1,%2,%3}, [%4];"
                 : "=r"(r[0]), "=r"(r[1]), "=r"(r[2]), "=r"(r[3]) : "r"(addr));
}
__device__ __forceinline__ void mma_f16(float* c, const uint32_t* a, const uint32_t* b) {
    asm volatile(
        "mma.sync.aligned.m16n8k16.row.col.f32.f16.f16.f32 "
        "{%0,%1,%2,%3}, {%4,%5,%6,%7}, {%8,%9}, {%0,%1,%2,%3};"
        : "+f"(c[0]), "+f"(c[1]), "+f"(c[2]), "+f"(c[3])
        : "r"(a[0]), "r"(a[1]), "r"(a[2]), "r"(a[3]), "r"(b[0]), "r"(b[1]));
}
__device__ __forceinline__ uint32_t cvtf16x2(float hi_, float lo_) {
    uint32_t r; asm("cvt.rn.f16x2.f32 %0, %1, %2;" : "=r"(r) : "f"(hi_), "f"(lo_)); return r;
}
__device__ __forceinline__ float ex2(float x) {
    float y; asm("ex2.approx.ftz.f32 %0, %1;" : "=f"(y) : "f"(x)); return y;
}
__device__ __forceinline__ void cp_async16(uint32_t dst, const void* src) {
    uint64_t g = (uint64_t)__cvta_generic_to_global(src);
    asm volatile("cp.async.cg.shared.global [%0], [%1], 16;" :: "r"(dst), "l"(g) : "memory");
}
__device__ __forceinline__ void cp_commit() {
    asm volatile("cp.async.commit_group;" ::: "memory");
}
template<int N> __device__ __forceinline__ void cp_wait() {
    asm volatile("cp.async.wait_group %0;" :: "n"(N) : "memory");
}

// ---------------- fused conversion + rope table ----------------
#define NX 1048576
#define NWQ 786432
#define NWO 262144
#define NTAB 65536   // T_ * 32 rope table entries
__global__ void conv_fused(const float4* __restrict__ x, const float4* __restrict__ wq,
                           const float4* __restrict__ wo)
{
    int i = blockIdx.x * blockDim.x + threadIdx.x;
    if (i < NX + NWQ + NWO) {
        const float4* s;
        uint2* d;
        int off;
        if (i < NX) { s = x; d = (uint2*)g_xf; off = i; }
        else if (i < NX + NWQ) { s = wq; d = (uint2*)g_Wqf; off = i - NX; }
        else { s = wo; d = (uint2*)g_Wof; off = i - NX - NWQ; }
        float4 f = s[off];
        d[off] = make_uint2(cvtf16x2(f.y, f.x), cvtf16x2(f.w, f.z));
    } else if (i < NX + NWQ + NWO + NTAB) {
        int idx = i - (NX + NWQ + NWO);
        int ii = idx & 31;
        int t = idx >> 5;
        double invd = exp(-(double)(2 * ii) / 64.0 * log(10000.0));
        float invf = (float)invd;
        float fr = (float)t * invf;
        double c_d, s_d;
        sincos((double)fr, &s_d, &c_d);
        g_cosT[t][ii] = (float)c_d;
        g_sinT[t][ii] = (float)s_d;
    }
}

// ============ fp16 tensor-core GEMM: C = A @ B^T + bias ============
// A single fp16 plane [M,K], B single fp16 plane [N,K] (n16 ldsm).
// 128x128 tile, K-chunk 32, 4-stage ring.
// MODE 0: fp32 C.  MODE 1: fused rope epilogue writing Q/K/V planes.
#define GP_STAGE 16384
__device__ __forceinline__ uint32_t sw_off(int row, int seg) {
    uint32_t L = ((uint32_t)(row >> 1) << 7) | ((uint32_t)(row & 1) << 6) | ((uint32_t)seg << 4);
    return L ^ ((L >> 3) & 0x70);
}

template<int MODE>
__global__ void __launch_bounds__(256, 2) tc_gemm_f16(
    const uint32_t* __restrict__ Af, const uint32_t* __restrict__ Bf,
    const float* __restrict__ bias, float* __restrict__ C,
    int M, int N, int K)
{
    extern __shared__ __align__(16) uint8_t dynsm[];
    uint32_t sbase = smem_u32(dynsm);

    int tid = threadIdx.x;
    int wid = tid >> 5, lane = tid & 31;
    int m0 = blockIdx.y << 7, n0 = blockIdx.x << 7;
    int wm = (wid >> 2) * 64, wn = (wid & 3) * 32;

    int rowoffA = (lane & 7) | (((lane >> 3) & 1) << 3);
    int seglA = lane >> 4;
    int rowaddB16 = (lane & 7) + ((lane >> 4) << 3);
    int segB01 = (lane >> 3) & 1;

    int K2 = K >> 1;
    int prow = tid >> 1;
    int ps0 = (tid & 1) * 2;
    const uint32_t* gp[2] = {Af + (size_t)(m0 + prow) * K2,
                             Bf + (size_t)(n0 + prow) * K2};

    float acc[4][4][4];
#pragma unroll
    for (int i = 0; i < 4; i++)
#pragma unroll
        for (int j = 0; j < 4; j++)
#pragma unroll
            for (int k = 0; k < 4; k++) acc[i][j][k] = 0.f;

    int iters = K >> 5;
    uint32_t o0 = sw_off(prow, ps0), o1 = sw_off(prow, ps0 + 1);

#pragma unroll
    for (int pre = 0; pre < 3; pre++) {
        uint32_t db = sbase + pre * GP_STAGE;
        int ko = pre * 16;
#pragma unroll
        for (int p = 0; p < 2; p++) {
            cp_async16(db + p * 8192 + o0, gp[p] + ko + ps0 * 4);
            cp_async16(db + p * 8192 + o1, gp[p] + ko + (ps0 + 1) * 4);
        }
        cp_commit();
    }

    int st = 0;
    for (int it = 0; it < iters; it++) {
        if (it < iters - 2) cp_wait<2>();
        else if (it == iters - 2) cp_wait<1>();
        else cp_wait<0>();
        __syncthreads();

        if (it + 3 < iters) {
            int pf = (st + 3) & 3;
            uint32_t db = sbase + pf * GP_STAGE;
            int ko = (it + 3) * 16;
#pragma unroll
            for (int p = 0; p < 2; p++) {
                cp_async16(db + p * 8192 + o0, gp[p] + ko + ps0 * 4);
                cp_async16(db + p * 8192 + o1, gp[p] + ko + (ps0 + 1) * 4);
            }
            cp_commit();
        }

        uint32_t sA = sbase + st * GP_STAGE;

#pragma unroll
        for (int h = 0; h < 2; h++) {
            uint32_t aF[4][4];
#pragma unroll
            for (int mt = 0; mt < 4; mt++)
                ldsm_x4(aF[mt], sA + sw_off(wm + mt * 16 + rowoffA, 2 * h + seglA));
#pragma unroll
            for (int nt16 = 0; nt16 < 2; nt16++) {
                uint32_t b4[4];
                ldsm_x4(b4, sA + 8192 +
                        sw_off(wn + nt16 * 16 + rowaddB16, 2 * h + segB01));
#pragma unroll
                for (int mt = 0; mt < 4; mt++) {
                    mma_f16(acc[mt][2 * nt16],     aF[mt], b4);
                    mma_f16(acc[mt][2 * nt16 + 1], aF[mt], b4 + 2);
                }
            }
        }
        st = (st + 1) & 3;
    }

    int rg = lane >> 2;
    int cg = (lane & 3) * 2;

    if (MODE == 0) {
#pragma unroll
        for (int nt = 0; nt < 4; nt++) {
            int n = n0 + wn + nt * 8 + cg;
            float b0v = bias[n], b1v = bias[n + 1];
#pragma unroll
            for (int mt = 0; mt < 4; mt++) {
                int m = m0 + wm + mt * 16 + rg;
                *(float2*)(C + (size_t)m * N + n) =
                    make_float2(acc[mt][nt][0] + b0v, acc[mt][nt][1] + b1v);
                *(float2*)(C + (size_t)(m + 8) * N + n) =
                    make_float2(acc[mt][nt][2] + b0v, acc[mt][nt][3] + b1v);
            }
        }
    } else {
        // fused rope epilogue: acc -> smem fp32 tile -> Q/K/V single fp16 planes
        float* tile = (float*)dynsm;   // [128][132]
        __syncthreads();
#pragma unroll
        for (int nt = 0; nt < 4; nt++) {
            int ncol = wn + nt * 8 + cg;
            float b0v = bias[n0 + ncol], b1v = bias[n0 + ncol + 1];
#pragma unroll
            for (int mt = 0; mt < 4; mt++) {
                int mr = wm + mt * 16 + rg;
                *(float2*)&tile[mr * 132 + ncol] =
                    make_float2(acc[mt][nt][0] + b0v, acc[mt][nt][1] + b1v);
                *(float2*)&tile[(mr + 8) * 132 + ncol] =
                    make_float2(acc[mt][nt][2] + b0v, acc[mt][nt][3] + b1v);
            }
        }
        __syncthreads();

        int i4 = tid & 15, rr4 = tid >> 4;
        int sec = n0 >> 10;                 // 0=Q,1=K,2=V
        int hbase = (n0 & 1023) >> 6;
#pragma unroll
        for (int w = 0; w < 8; w++) {
            int r = rr4 + w * 16;
            int m = m0 + r;
            int b = m >> 11, t = m & 2047;
            float cs0 = g_cosT[t][2 * i4], cs1 = g_cosT[t][2 * i4 + 1];
            float sn0 = g_sinT[t][2 * i4], sn1 = g_sinT[t][2 * i4 + 1];
#pragma unroll
            for (int hh = 0; hh < 2; hh++) {
                int hgl = hbase + hh;
                float2 x1 = *(float2*)&tile[r * 132 + hh * 64 + 2 * i4];
                float2 x2 = *(float2*)&tile[r * 132 + hh * 64 + 32 + 2 * i4];
                size_t row32 = ((size_t)(b * H_ + hgl) * T_ + t) * 32;
                if (sec == 0) {
                    g_Qf[row32 + i4] =
                        cvtf16x2((x1.y * cs1 - x2.y * sn1) * QSCALE,
                                 (x1.x * cs0 - x2.x * sn0) * QSCALE);
                    g_Qf[row32 + 16 + i4] =
                        cvtf16x2((x1.y * sn1 + x2.y * cs1) * QSCALE,
                                 (x1.x * sn0 + x2.x * cs0) * QSCALE);
                } else if (sec == 1) {
                    g_Kf[row32 + i4] =
                        cvtf16x2(x1.y * cs1 - x2.y * sn1, x1.x * cs0 - x2.x * sn0);
                    g_Kf[row32 + 16 + i4] =
                        cvtf16x2(x1.y * sn1 + x2.y * cs1, x1.x * sn0 + x2.x * cs0);
                } else {
                    g_Vf[row32 + i4]      = cvtf16x2(x1.y, x1.x);
                    g_Vf[row32 + 16 + i4] = cvtf16x2(x2.y, x2.x);
                }
            }
        }
    }
}

// ============ tensor-core flash attention (pair-pipelined) ============
// S: single-fp16 Q x K. P: fp16. V: single fp16. l via ones column.
// BR=128 (8 warps x 16 rows), BC=64. 3 ring slots of 2 tiles; 1 barrier / 128 keys.
#define AT_PLANE 9216
#define AT_TILE  (2 * AT_PLANE)     // K+V planes, one 64-key tile
#define AT_PAIR  (2 * AT_TILE)
#define AT_SMEM  (3 * AT_PAIR)      // 110592

__device__ __forceinline__ void process_tile(
    uint32_t tbase, int kt, int qt, int wr0, int rg, int tg,
    bool g0, bool g1, bool wanyg, int wmaxrow,
    int rowaddK, int segoffK, int l15, int vcol,
    const uint32_t (&qf)[4][4], float (&oacc)[8][4], float (&oaccl)[4])
{
    if (kt * 64 > wmaxrow && !wanyg) return;
    uint32_t sK = tbase;
    uint32_t sV = tbase + AT_PLANE;

    float sc[8][4];
#pragma unroll
    for (int j = 0; j < 8; j++)
#pragma unroll
        for (int c = 0; c < 4; c++) sc[j][c] = -SOFTMAX_SHIFT;

    // ---- S half A (cols 0..31) ----
#pragma unroll
    for (int kc = 0; kc < 4; kc++)
#pragma unroll
        for (int jp = 0; jp < 2; jp++) {
            uint32_t b4[4];
            ldsm_x4(b4, sK + (uint32_t)((jp * 16 + rowaddK) * 144 + kc * 32 + segoffK));
            mma_f16(sc[2 * jp],     qf[kc], b4);
            mma_f16(sc[2 * jp + 1], qf[kc], b4 + 2);
        }
    // ---- S half B (cols 32..63) ----
#pragma unroll
    for (int kc = 0; kc < 4; kc++)
#pragma unroll
        for (int jp = 2; jp < 4; jp++) {
            uint32_t b4[4];
            ldsm_x4(b4, sK + (uint32_t)((jp * 16 + rowaddK) * 144 + kc * 32 + segoffK));
            mma_f16(sc[2 * jp],     qf[kc], b4);
            mma_f16(sc[2 * jp + 1], qf[kc], b4 + 2);
        }

    bool fullcausal = (kt * 64 + 63 <= qt * 128 + wr0);
    int row0 = qt * 128 + wr0 + rg;
    uint32_t pfr[4][4];

    // ---- softmax+pack half A ----
#pragma unroll
    for (int j = 0; j < 4; j++) {
        if (!fullcausal) {
            int colb = kt * 64 + j * 8 + tg * 2;
            if (!g0) {
                if (colb > row0)     sc[j][0] = -1e30f;
                if (colb + 1 > row0) sc[j][1] = -1e30f;
            }
            if (!g1) {
                if (colb > row0 + 8)     sc[j][2] = -1e30f;
                if (colb + 1 > row0 + 8) sc[j][3] = -1e30f;
            }
        }
        float p0 = ex2(sc[j][0]), p1 = ex2(sc[j][1]);
        float p2 = ex2(sc[j][2]), p3 = ex2(sc[j][3]);
        pfr[j >> 1][(j & 1) * 2 + 0] = cvtf16x2(p1, p0);
        pfr[j >> 1][(j & 1) * 2 + 1] = cvtf16x2(p3, p2);
    }

    // ---- PV half A (kk 0,1) incl. ones column ----
#pragma unroll
    for (int kk = 0; kk < 2; kk++) {
#pragma unroll
        for (int jp = 0; jp < 4; jp++) {
            uint32_t v4[4];
            ldsm_x4_t(v4, sV + (uint32_t)((kk * 16 + l15) * 144 + jp * 32 + vcol));
            mma_f16(oacc[2 * jp],     pfr[kk], v4);
            mma_f16(oacc[2 * jp + 1], pfr[kk], v4 + 2);
        }
        uint32_t v1[4];
        ldsm_x4_t(v1, sV + (uint32_t)((kk * 16 + l15) * 144 + 128));
        mma_f16(oaccl, pfr[kk], v1);
    }

    // ---- softmax+pack half B ----
#pragma unroll
    for (int j = 4; j < 8; j++) {
        if (!fullcausal) {
            int colb = kt * 64 + j * 8 + tg * 2;
            if (!g0) {
                if (colb > row0)     sc[j][0] = -1e30f;
                if (colb + 1 > row0) sc[j][1] = -1e30f;
            }
            if (!g1) {
                if (colb > row0 + 8)     sc[j][2] = -1e30f;
                if (colb + 1 > row0 + 8) sc[j][3] = -1e30f;
            }
        }
        float p0 = ex2(sc[j][0]), p1 = ex2(sc[j][1]);
        float p2 = ex2(sc[j][2]), p3 = ex2(sc[j][3]);
        pfr[j >> 1][(j & 1) * 2 + 0] = cvtf16x2(p1, p0);
        pfr[j >> 1][(j & 1) * 2 + 1] = cvtf16x2(p3, p2);
    }

    // ---- PV half B (kk 2,3) incl. ones column ----
#pragma unroll
    for (int kk = 2; kk < 4; kk++) {
#pragma unroll
        for (int jp = 0; jp < 4; jp++) {
            uint32_t v4[4];
            ldsm_x4_t(v4, sV + (uint32_t)((kk * 16 + l15) * 144 + jp * 32 + vcol));
            mma_f16(oacc[2 * jp],     pfr[kk], v4);
            mma_f16(oacc[2 * jp + 1], pfr[kk], v4 + 2);
        }
        uint32_t v1[4];
        ldsm_x4_t(v1, sV + (uint32_t)((kk * 16 + l15) * 144 + 128));
        mma_f16(oaccl, pfr[kk], v1);
    }
}

__global__ void __launch_bounds__(256, 2) attn_kernel(const int* __restrict__ ids)
{
    extern __shared__ __align__(16) uint8_t dynsm[];
    __shared__ float gq[128];
    uint32_t sbase = smem_u32(dynsm);

    int tid = threadIdx.x;
    int wid = tid >> 5, lane = tid & 31;
    int rg = lane >> 2, tg = lane & 3;
    int qt = gridDim.x - 1 - blockIdx.x;
    int h = blockIdx.y, b = blockIdx.z;
    int wr0 = wid * 16;

    size_t bh = ((size_t)b * H_ + h) * T_;

    // ones-column pad: V plane col64 = 1.0h (6 tile buffers x 64 rows)
    for (int i = tid; i < 384; i += 256) {
        uint8_t* pp = dynsm + (i >> 6) * AT_TILE + (i & 63) * 144 + 128;
        *(uint4*)(pp + AT_PLANE) = make_uint4(0x00003C00u, 0u, 0u, 0u);
    }

    // Q fragments (single fp16, pre-scaled)
    uint32_t qf[4][4];
#pragma unroll
    for (int kc = 0; kc < 4; kc++)
#pragma unroll
        for (int part = 0; part < 4; part++) {
            size_t row = bh + qt * 128 + wr0 + rg + ((part & 1) << 3);
            int du = kc * 8 + tg + ((part >> 1) << 2);
            qf[kc][part] = g_Qf[row * 32 + du];
        }

    int myflag = 0;
    if (tid < 128) {
        int id = ids[(size_t)b * T_ + (size_t)qt * 128 + tid];
        myflag = (id >= 2 && id <= 7) ? 1 : 0;
        gq[tid] = (float)myflag;
    }
    int anyg = __syncthreads_or(myflag);

    bool g0 = gq[wr0 + rg] > 0.5f;
    bool g1 = gq[wr0 + rg + 8] > 0.5f;
    bool wanyg = __any_sync(0xffffffffu, g0 || g1);

    float oacc[8][4];
#pragma unroll
    for (int j = 0; j < 8; j++)
#pragma unroll
        for (int c = 0; c < 4; c++) oacc[j][c] = 0.f;
    float oaccl[4] = {0.f, 0.f, 0.f, 0.f};

    int rowaddK = (lane & 7) + ((lane >> 4) << 3);
    int segoffK = ((lane >> 3) & 1) * 16;
    int l15 = lane & 15;
    int vcol = (lane >> 4) * 16;

    int ktEnd = anyg ? (T_ / 64) : (2 * qt + 2);   // always even
    int P = ktEnd >> 1;
    int wmaxrow = qt * 128 + wr0 + 15;

    int trow = tid >> 2;
    int tcs = (tid & 3) * 2;
    uint32_t dboff = trow * 144 + tcs * 16;

    // prefetch pairs 0 and 1 (commit one group per pair, even if empty)
#pragma unroll
    for (int pre = 0; pre < 2; pre++) {
        if (pre < P) {
#pragma unroll
            for (int sub = 0; sub < 2; sub++) {
                int kt = 2 * pre + sub;
                size_t gr = (bh + (size_t)kt * 64 + trow) * 32 + tcs * 4;
                uint32_t db = sbase + pre * AT_PAIR + sub * AT_TILE + dboff;
                cp_async16(db, g_Kf + gr);
                cp_async16(db + 16, g_Kf + gr + 4);
                cp_async16(db + AT_PLANE, g_Vf + gr);
                cp_async16(db + AT_PLANE + 16, g_Vf + gr + 4);
            }
        }
        cp_commit();
    }

    int slot = 0;
    for (int p = 0; p < P; p++) {
        if (p < P - 1) cp_wait<1>(); else cp_wait<0>();
        __syncthreads();

        if (p + 2 < P) {
            int ps = slot + 2; if (ps >= 3) ps -= 3;
#pragma unroll
            for (int sub = 0; sub < 2; sub++) {
                int kt = 2 * (p + 2) + sub;
                size_t gr = (bh + (size_t)kt * 64 + trow) * 32 + tcs * 4;
                uint32_t db = sbase + ps * AT_PAIR + sub * AT_TILE + dboff;
                cp_async16(db, g_Kf + gr);
                cp_async16(db + 16, g_Kf + gr + 4);
                cp_async16(db + AT_PLANE, g_Vf + gr);
                cp_async16(db + AT_PLANE + 16, g_Vf + gr + 4);
            }
        }
        cp_commit();

        uint32_t base = sbase + slot * AT_PAIR;
        process_tile(base, 2 * p, qt, wr0, rg, tg, g0, g1, wanyg, wmaxrow,
                     rowaddK, segoffK, l15, vcol, qf, oacc, oaccl);
        process_tile(base + AT_TILE, 2 * p + 1, qt, wr0, rg, tg, g0, g1, wanyg, wmaxrow,
                     rowaddK, segoffK, l15, vcol, qf, oacc, oaccl);

        slot = (slot == 2) ? 0 : slot + 1;
    }

    // ---- epilogue: l from ones column; write O single fp16 plane ----
    int src = lane & ~3;
    float l0 = __shfl_sync(0xffffffffu, oaccl[0], src);
    float l1 = __shfl_sync(0xffffffffu, oaccl[2], src);
    float inv0 = 1.0f / l0;
    float inv1 = 1.0f / l1;
    int q0 = qt * 128 + wr0 + rg;
#pragma unroll
    for (int j = 0; j < 8; j++) {
        int cu = h * 32 + j * 4 + tg;
        g_Of[(size_t)(b * T_ + q0) * 512 + cu] =
            cvtf16x2(oacc[j][1] * inv0, oacc[j][0] * inv0);
        g_Of[(size_t)(b * T_ + q0 + 8) * 512 + cu] =
            cvtf16x2(oacc[j][3] * inv1, oacc[j][2] * inv1);
    }
}

// ---------------- launch ----------------
extern "C" void kernel_launch(void* const* d_in, const int* in_sizes, int n_in,
                              void* d_out, int out_size)
{
    const float* x    = (const float*)d_in[0];
    const int*   ids  = (const int*)d_in[1];
    const float* Wqkv = (const float*)d_in[2];
    const float* bqkv = (const float*)d_in[3];
    const float* Wout = (const float*)d_in[4];
    const float* bout = (const float*)d_in[5];
    float* out = (float*)d_out;

    uint32_t *xf, *wqf, *wof, *of;
    cudaGetSymbolAddress((void**)&xf, g_xf);
    cudaGetSymbolAddress((void**)&wqf, g_Wqf);
    cudaGetSymbolAddress((void**)&wof, g_Wof);
    cudaGetSymbolAddress((void**)&of, g_Of);

    // QKV (MODE1): epilogue tile needs 128*132*4 = 67584 B (> 4*GP_STAGE)
    cudaFuncSetAttribute(tc_gemm_f16<1>, cudaFuncAttributeMaxDynamicSharedMemorySize, 67584);
    cudaFuncSetAttribute(tc_gemm_f16<0>, cudaFuncAttributeMaxDynamicSharedMemorySize, 4 * GP_STAGE);
    cudaFuncSetAttribute(attn_kernel, cudaFuncAttributeMaxDynamicSharedMemorySize, AT_SMEM);

    // 0) fused conversions + rope table
    conv_fused<<<(NX + NWQ + NWO + NTAB + 255) / 256, 256>>>(
        (const float4*)x, (const float4*)Wqkv, (const float4*)Wout);

    // 1) QKV projection (single x single) with fused rope epilogue
    {
        dim3 grid(3 * D_ / 128, (B_ * T_) / 128);
        tc_gemm_f16<1><<<grid, 256, 67584>>>(xf, wqf, bqkv, nullptr,
                                             B_ * T_, 3 * D_, D_);
    }

    // 2) attention
    {
        dim3 grid(T_ / 128, H_, B_);
        attn_kernel<<<grid, 256, AT_SMEM>>>(ids);
    }

    // 3) output projection (single x single)
    {
        dim3 grid(D_ / 128, (B_ * T_) / 128);
        tc_gemm_f16<0><<<grid, 256, 4 * GP_STAGE>>>(of, wof, bout, out,
                                                    B_ * T_, D_, D_);
    }
}

// round 16
// speedup vs baseline: 1.0058x; 1.0058x over previous
#include <cuda_runtime.h>
#include <cuda_bf16.h>
#include <cuda_fp16.h>
#include <math.h>
#include <stdint.h>

#define B_ 2
#define T_ 2048
#define D_ 1024
#define H_ 16
#define HD_ 64
#define QSCALE (0.125f * 1.4426950408889634f)   // 1/sqrt(64) * log2(e)
#define SOFTMAX_SHIFT 4.0f

// ---------------- scratch ----------------
__device__ uint32_t g_xf[2097152];                         // x fp16 single [4096,512]
__device__ uint32_t g_Wqf[1572864];                        // Wqkv fp16 single [3072,512]
__device__ uint32_t g_Wof[524288];                         // Wout fp16 single [1024,512]
__device__ uint32_t g_Qf[2097152];                         // [B,H,T,HD] fp16 single (scaled)
__device__ uint32_t g_Kf[2097152];                         // fp16 single
__device__ uint32_t g_Vf[2097152];                         // fp16 single
__device__ uint32_t g_Of[2097152];                         // [B,T,H*HD] fp16 single
__device__ float g_cosT[T_][32];
__device__ float g_sinT[T_][32];

// ================= helpers =================
__device__ __forceinline__ uint32_t smem_u32(const void* p) {
    uint32_t a;
    asm("{ .reg .u64 t; cvta.to.shared.u64 t, %1; cvt.u32.u64 %0, t; }" : "=r"(a) : "l"(p));
    return a;
}
__device__ __forceinline__ void ldsm_x4(uint32_t* r, uint32_t addr) {
    asm volatile("ldmatrix.sync.aligned.m8n8.x4.shared.b16 {%0,%1,%2,%3}, [%4];"
                 : "=r"(r[0]), "=r"(r[1]), "=r"(r[2]), "=r"(r[3]) : "r"(addr));
}
__device__ __forceinline__ void ldsm_x4_t(uint32_t* r, uint32_t addr) {
    asm volatile("ldmatrix.sync.aligned.m8n8.x4.trans.shared.b16 {%0,%1,%2,%3}, [%4];"
                 : "=r"(r[0]), "=r"(r[1]), "=r"(r[2]), "=r"(r[3]) : "r"(addr));
}
__device__ __forceinline__ void mma_f16(float* c, const uint32_t* a, const uint32_t* b) {
    asm volatile(
        "mma.sync.aligned.m16n8k16.row.col.f32.f16.f16.f32 "
        "{%0,%1,%2,%3}, {%4,%5,%6,%7}, {%8,%9}, {%0,%1,%2,%3};"
        : "+f"(c[0]), "+f"(c[1]), "+f"(c[2]), "+f"(c[3])
        : "r"(a[0]), "r"(a[1]), "r"(a[2]), "r"(a[3]), "r"(b[0]), "r"(b[1]));
}
__device__ __forceinline__ uint32_t cvtf16x2(float hi_, float lo_) {
    uint32_t r; asm("cvt.rn.f16x2.f32 %0, %1, %2;" : "=r"(r) : "f"(hi_), "f"(lo_)); return r;
}
__device__ __forceinline__ float ex2(float x) {
    float y; asm("ex2.approx.ftz.f32 %0, %1;" : "=f"(y) : "f"(x)); return y;
}
__device__ __forceinline__ void cp_async16(uint32_t dst, const void* src) {
    uint64_t g = (uint64_t)__cvta_generic_to_global(src);
    asm volatile("cp.async.cg.shared.global [%0], [%1], 16;" :: "r"(dst), "l"(g) : "memory");
}
__device__ __forceinline__ void cp_commit() {
    asm volatile("cp.async.commit_group;" ::: "memory");
}
template<int N> __device__ __forceinline__ void cp_wait() {
    asm volatile("cp.async.wait_group %0;" :: "n"(N) : "memory");
}

// ---------------- fused conversion + rope table ----------------
#define NX 1048576
#define NWQ 786432
#define NWO 262144
#define NTAB 65536
__global__ void conv_fused(const float4* __restrict__ x, const float4* __restrict__ wq,
                           const float4* __restrict__ wo)
{
    int i = blockIdx.x * blockDim.x + threadIdx.x;
    if (i < NX + NWQ + NWO) {
        const float4* s;
        uint2* d;
        int off;
        if (i < NX) { s = x; d = (uint2*)g_xf; off = i; }
        else if (i < NX + NWQ) { s = wq; d = (uint2*)g_Wqf; off = i - NX; }
        else { s = wo; d = (uint2*)g_Wof; off = i - NX - NWQ; }
        float4 f = s[off];
        d[off] = make_uint2(cvtf16x2(f.y, f.x), cvtf16x2(f.w, f.z));
    } else if (i < NX + NWQ + NWO + NTAB) {
        int idx = i - (NX + NWQ + NWO);
        int ii = idx & 31;
        int t = idx >> 5;
        double invd = exp(-(double)(2 * ii) / 64.0 * log(10000.0));
        float invf = (float)invd;
        float fr = (float)t * invf;
        double c_d, s_d;
        sincos((double)fr, &s_d, &c_d);
        g_cosT[t][ii] = (float)c_d;
        g_sinT[t][ii] = (float)s_d;
    }
}

// ============ fp16 tensor-core GEMM: C = A @ B^T + bias ============
// A single fp16 plane [M,K], B single fp16 plane [N,K] (n16 ldsm).
// 128x128 tile, K-chunk 32, 4-stage ring.
// MODE 0: fp32 C.  MODE 1: fused rope epilogue writing Q/K/V planes.
#define GP_STAGE 16384
__device__ __forceinline__ uint32_t sw_off(int row, int seg) {
    uint32_t L = ((uint32_t)(row >> 1) << 7) | ((uint32_t)(row & 1) << 6) | ((uint32_t)seg << 4);
    return L ^ ((L >> 3) & 0x70);
}

template<int MODE>
__global__ void __launch_bounds__(256, 2) tc_gemm_f16(
    const uint32_t* __restrict__ Af, const uint32_t* __restrict__ Bf,
    const float* __restrict__ bias, float* __restrict__ C,
    int M, int N, int K)
{
    extern __shared__ __align__(16) uint8_t dynsm[];
    uint32_t sbase = smem_u32(dynsm);

    int tid = threadIdx.x;
    int wid = tid >> 5, lane = tid & 31;
    int m0 = blockIdx.y << 7, n0 = blockIdx.x << 7;
    int wm = (wid >> 2) * 64, wn = (wid & 3) * 32;

    int rowoffA = (lane & 7) | (((lane >> 3) & 1) << 3);
    int seglA = lane >> 4;
    int rowaddB16 = (lane & 7) + ((lane >> 4) << 3);
    int segB01 = (lane >> 3) & 1;

    int K2 = K >> 1;
    int prow = tid >> 1;
    int ps0 = (tid & 1) * 2;
    const uint32_t* gp[2] = {Af + (size_t)(m0 + prow) * K2,
                             Bf + (size_t)(n0 + prow) * K2};

    float acc[4][4][4];
#pragma unroll
    for (int i = 0; i < 4; i++)
#pragma unroll
        for (int j = 0; j < 4; j++)
#pragma unroll
            for (int k = 0; k < 4; k++) acc[i][j][k] = 0.f;

    int iters = K >> 5;
    uint32_t o0 = sw_off(prow, ps0), o1 = sw_off(prow, ps0 + 1);

#pragma unroll
    for (int pre = 0; pre < 3; pre++) {
        uint32_t db = sbase + pre * GP_STAGE;
        int ko = pre * 16;
#pragma unroll
        for (int p = 0; p < 2; p++) {
            cp_async16(db + p * 8192 + o0, gp[p] + ko + ps0 * 4);
            cp_async16(db + p * 8192 + o1, gp[p] + ko + (ps0 + 1) * 4);
        }
        cp_commit();
    }

    int st = 0;
    for (int it = 0; it < iters; it++) {
        if (it < iters - 2) cp_wait<2>();
        else if (it == iters - 2) cp_wait<1>();
        else cp_wait<0>();
        __syncthreads();

        if (it + 3 < iters) {
            int pf = (st + 3) & 3;
            uint32_t db = sbase + pf * GP_STAGE;
            int ko = (it + 3) * 16;
#pragma unroll
            for (int p = 0; p < 2; p++) {
                cp_async16(db + p * 8192 + o0, gp[p] + ko + ps0 * 4);
                cp_async16(db + p * 8192 + o1, gp[p] + ko + (ps0 + 1) * 4);
            }
            cp_commit();
        }

        uint32_t sA = sbase + st * GP_STAGE;

#pragma unroll
        for (int h = 0; h < 2; h++) {
            uint32_t aF[4][4];
#pragma unroll
            for (int mt = 0; mt < 4; mt++)
                ldsm_x4(aF[mt], sA + sw_off(wm + mt * 16 + rowoffA, 2 * h + seglA));
#pragma unroll
            for (int nt16 = 0; nt16 < 2; nt16++) {
                uint32_t b4[4];
                ldsm_x4(b4, sA + 8192 +
                        sw_off(wn + nt16 * 16 + rowaddB16, 2 * h + segB01));
#pragma unroll
                for (int mt = 0; mt < 4; mt++) {
                    mma_f16(acc[mt][2 * nt16],     aF[mt], b4);
                    mma_f16(acc[mt][2 * nt16 + 1], aF[mt], b4 + 2);
                }
            }
        }
        st = (st + 1) & 3;
    }

    int rg = lane >> 2;
    int cg = (lane & 3) * 2;

    if (MODE == 0) {
#pragma unroll
        for (int nt = 0; nt < 4; nt++) {
            int n = n0 + wn + nt * 8 + cg;
            float b0v = bias[n], b1v = bias[n + 1];
#pragma unroll
            for (int mt = 0; mt < 4; mt++) {
                int m = m0 + wm + mt * 16 + rg;
                *(float2*)(C + (size_t)m * N + n) =
                    make_float2(acc[mt][nt][0] + b0v, acc[mt][nt][1] + b1v);
                *(float2*)(C + (size_t)(m + 8) * N + n) =
                    make_float2(acc[mt][nt][2] + b0v, acc[mt][nt][3] + b1v);
            }
        }
    } else {
        float* tile = (float*)dynsm;   // [128][132]
        __syncthreads();
#pragma unroll
        for (int nt = 0; nt < 4; nt++) {
            int ncol = wn + nt * 8 + cg;
            float b0v = bias[n0 + ncol], b1v = bias[n0 + ncol + 1];
#pragma unroll
            for (int mt = 0; mt < 4; mt++) {
                int mr = wm + mt * 16 + rg;
                *(float2*)&tile[mr * 132 + ncol] =
                    make_float2(acc[mt][nt][0] + b0v, acc[mt][nt][1] + b1v);
                *(float2*)&tile[(mr + 8) * 132 + ncol] =
                    make_float2(acc[mt][nt][2] + b0v, acc[mt][nt][3] + b1v);
            }
        }
        __syncthreads();

        int i4 = tid & 15, rr4 = tid >> 4;
        int sec = n0 >> 10;                 // 0=Q,1=K,2=V
        int hbase = (n0 & 1023) >> 6;
#pragma unroll
        for (int w = 0; w < 8; w++) {
            int r = rr4 + w * 16;
            int m = m0 + r;
            int b = m >> 11, t = m & 2047;
            float cs0 = g_cosT[t][2 * i4], cs1 = g_cosT[t][2 * i4 + 1];
            float sn0 = g_sinT[t][2 * i4], sn1 = g_sinT[t][2 * i4 + 1];
#pragma unroll
            for (int hh = 0; hh < 2; hh++) {
                int hgl = hbase + hh;
                float2 x1 = *(float2*)&tile[r * 132 + hh * 64 + 2 * i4];
                float2 x2 = *(float2*)&tile[r * 132 + hh * 64 + 32 + 2 * i4];
                size_t row32 = ((size_t)(b * H_ + hgl) * T_ + t) * 32;
                if (sec == 0) {
                    g_Qf[row32 + i4] =
                        cvtf16x2((x1.y * cs1 - x2.y * sn1) * QSCALE,
                                 (x1.x * cs0 - x2.x * sn0) * QSCALE);
                    g_Qf[row32 + 16 + i4] =
                        cvtf16x2((x1.y * sn1 + x2.y * cs1) * QSCALE,
                                 (x1.x * sn0 + x2.x * cs0) * QSCALE);
                } else if (sec == 1) {
                    g_Kf[row32 + i4] =
                        cvtf16x2(x1.y * cs1 - x2.y * sn1, x1.x * cs0 - x2.x * sn0);
                    g_Kf[row32 + 16 + i4] =
                        cvtf16x2(x1.y * sn1 + x2.y * cs1, x1.x * sn0 + x2.x * cs0);
                } else {
                    g_Vf[row32 + i4]      = cvtf16x2(x1.y, x1.x);
                    g_Vf[row32 + 16 + i4] = cvtf16x2(x2.y, x2.x);
                }
            }
        }
    }
}

// ============ tensor-core flash attention ============
// S: single-fp16 Q x K. P: fp16. V: single fp16. l via ones column.
// BR=128 (8 warps x 16 rows), BC=64. 4-stage ring, wait<2> (distance-3 prefetch).
#define AT_PLANE 9216
#define AT_STAGE (2 * AT_PLANE)
#define AT_SMEM  (4 * AT_STAGE)     // 73728

__global__ void __launch_bounds__(256, 2) attn_kernel(const int* __restrict__ ids)
{
    extern __shared__ __align__(16) uint8_t dynsm[];
    __shared__ float gq[128];
    uint32_t sbase = smem_u32(dynsm);

    int tid = threadIdx.x;
    int wid = tid >> 5, lane = tid & 31;
    int rg = lane >> 2, tg = lane & 3;
    int qt = gridDim.x - 1 - blockIdx.x;
    int h = blockIdx.y, b = blockIdx.z;
    int wr0 = wid * 16;

    size_t bh = ((size_t)b * H_ + h) * T_;

    // ones-column pad: V plane col64 = 1.0h (4 stages x 64 rows)
    if (tid < 256) {
        uint8_t* pp = dynsm + (tid >> 6) * AT_STAGE + (tid & 63) * 144 + 128;
        *(uint4*)(pp + AT_PLANE) = make_uint4(0x00003C00u, 0u, 0u, 0u);
    }

    // Q fragments (single fp16, pre-scaled)
    uint32_t qf[4][4];
#pragma unroll
    for (int kc = 0; kc < 4; kc++)
#pragma unroll
        for (int part = 0; part < 4; part++) {
            size_t row = bh + qt * 128 + wr0 + rg + ((part & 1) << 3);
            int du = kc * 8 + tg + ((part >> 1) << 2);
            qf[kc][part] = g_Qf[row * 32 + du];
        }

    int myflag = 0;
    if (tid < 128) {
        int id = ids[(size_t)b * T_ + (size_t)qt * 128 + tid];
        myflag = (id >= 2 && id <= 7) ? 1 : 0;
        gq[tid] = (float)myflag;
    }
    int anyg = __syncthreads_or(myflag);

    bool g0 = gq[wr0 + rg] > 0.5f;
    bool g1 = gq[wr0 + rg + 8] > 0.5f;
    bool wanyg = __any_sync(0xffffffffu, g0 || g1);

    float oacc[8][4];
#pragma unroll
    for (int j = 0; j < 8; j++)
#pragma unroll
        for (int c = 0; c < 4; c++) oacc[j][c] = 0.f;
    float oaccl[4] = {0.f, 0.f, 0.f, 0.f};

    int rowaddK = (lane & 7) + ((lane >> 4) << 3);
    int segoffK = ((lane >> 3) & 1) * 16;
    int l15 = lane & 15;
    int vcol = (lane >> 4) * 16;

    int ktEnd = anyg ? (T_ / 64) : (2 * qt + 2);
    int wmaxrow = qt * 128 + wr0 + 15;

    int trow = tid >> 2;
    int tcs = (tid & 3) * 2;
    const uint32_t* gpl[2] = {g_Kf, g_Vf};
    uint32_t dboff = trow * 144 + tcs * 16;

    // prefetch tiles 0..2 (commit per tile; empty groups if past end)
#pragma unroll
    for (int pre = 0; pre < 3; pre++) {
        if (pre < ktEnd) {
            size_t gr = (bh + (size_t)pre * 64 + trow) * 32 + tcs * 4;
            uint32_t db = sbase + pre * AT_STAGE + dboff;
#pragma unroll
            for (int p = 0; p < 2; p++) {
                cp_async16(db + p * AT_PLANE, gpl[p] + gr);
                cp_async16(db + p * AT_PLANE + 16, gpl[p] + gr + 4);
            }
        }
        cp_commit();
    }

    int st = 0;
    for (int kt = 0; kt < ktEnd; kt++) {
        if (kt < ktEnd - 2) cp_wait<2>();
        else if (kt == ktEnd - 2) cp_wait<1>();
        else cp_wait<0>();
        __syncthreads();

        if (kt + 3 < ktEnd) {
            int pf = (st + 3) & 3;
            size_t gr = (bh + (size_t)(kt + 3) * 64 + trow) * 32 + tcs * 4;
            uint32_t db = sbase + pf * AT_STAGE + dboff;
#pragma unroll
            for (int p = 0; p < 2; p++) {
                cp_async16(db + p * AT_PLANE, gpl[p] + gr);
                cp_async16(db + p * AT_PLANE + 16, gpl[p] + gr + 4);
            }
            cp_commit();
        }

        if (kt * 64 > wmaxrow && !wanyg) { st = (st + 1) & 3; continue; }

        uint32_t sK = sbase + st * AT_STAGE;
        uint32_t sV = sbase + st * AT_STAGE + AT_PLANE;

        float sc[8][4];
#pragma unroll
        for (int j = 0; j < 8; j++)
#pragma unroll
            for (int c = 0; c < 4; c++) sc[j][c] = -SOFTMAX_SHIFT;

        // ---- S half A (cols 0..31, jp 0,1) ----
#pragma unroll
        for (int kc = 0; kc < 4; kc++)
#pragma unroll
            for (int jp = 0; jp < 2; jp++) {
                uint32_t b4[4];
                ldsm_x4(b4, sK + (uint32_t)((jp * 16 + rowaddK) * 144 + kc * 32 + segoffK));
                mma_f16(sc[2 * jp],     qf[kc], b4);
                mma_f16(sc[2 * jp + 1], qf[kc], b4 + 2);
            }
        // ---- S half B (cols 32..63, jp 2,3) ----
#pragma unroll
        for (int kc = 0; kc < 4; kc++)
#pragma unroll
            for (int jp = 2; jp < 4; jp++) {
                uint32_t b4[4];
                ldsm_x4(b4, sK + (uint32_t)((jp * 16 + rowaddK) * 144 + kc * 32 + segoffK));
                mma_f16(sc[2 * jp],     qf[kc], b4);
                mma_f16(sc[2 * jp + 1], qf[kc], b4 + 2);
            }

        bool fullcausal = (kt * 64 + 63 <= qt * 128 + wr0);
        int row0 = qt * 128 + wr0 + rg;
        uint32_t pfr[4][4];

        // ---- softmax+pack half A (overlaps half-B MMAs) ----
#pragma unroll
        for (int j = 0; j < 4; j++) {
            if (!fullcausal) {
                int colb = kt * 64 + j * 8 + tg * 2;
                if (!g0) {
                    if (colb > row0)     sc[j][0] = -1e30f;
                    if (colb + 1 > row0) sc[j][1] = -1e30f;
                }
                if (!g1) {
                    if (colb > row0 + 8)     sc[j][2] = -1e30f;
                    if (colb + 1 > row0 + 8) sc[j][3] = -1e30f;
                }
            }
            float p0 = ex2(sc[j][0]), p1 = ex2(sc[j][1]);
            float p2 = ex2(sc[j][2]), p3 = ex2(sc[j][3]);
            pfr[j >> 1][(j & 1) * 2 + 0] = cvtf16x2(p1, p0);
            pfr[j >> 1][(j & 1) * 2 + 1] = cvtf16x2(p3, p2);
        }

        // ---- PV half A (kk 0,1) incl. ones column ----
#pragma unroll
        for (int kk = 0; kk < 2; kk++) {
#pragma unroll
            for (int jp = 0; jp < 4; jp++) {
                uint32_t v4[4];
                ldsm_x4_t(v4, sV + (uint32_t)((kk * 16 + l15) * 144 + jp * 32 + vcol));
                mma_f16(oacc[2 * jp],     pfr[kk], v4);
                mma_f16(oacc[2 * jp + 1], pfr[kk], v4 + 2);
            }
            uint32_t v1[4];
            ldsm_x4_t(v1, sV + (uint32_t)((kk * 16 + l15) * 144 + 128));
            mma_f16(oaccl, pfr[kk], v1);
        }

        // ---- softmax+pack half B (overlaps PV-A MMAs) ----
#pragma unroll
        for (int j = 4; j < 8; j++) {
            if (!fullcausal) {
                int colb = kt * 64 + j * 8 + tg * 2;
                if (!g0) {
                    if (colb > row0)     sc[j][0] = -1e30f;
                    if (colb + 1 > row0) sc[j][1] = -1e30f;
                }
                if (!g1) {
                    if (colb > row0 + 8)     sc[j][2] = -1e30f;
                    if (colb + 1 > row0 + 8) sc[j][3] = -1e30f;
                }
            }
            float p0 = ex2(sc[j][0]), p1 = ex2(sc[j][1]);
            float p2 = ex2(sc[j][2]), p3 = ex2(sc[j][3]);
            pfr[j >> 1][(j & 1) * 2 + 0] = cvtf16x2(p1, p0);
            pfr[j >> 1][(j & 1) * 2 + 1] = cvtf16x2(p3, p2);
        }

        // ---- PV half B (kk 2,3) incl. ones column ----
#pragma unroll
        for (int kk = 2; kk < 4; kk++) {
#pragma unroll
            for (int jp = 0; jp < 4; jp++) {
                uint32_t v4[4];
                ldsm_x4_t(v4, sV + (uint32_t)((kk * 16 + l15) * 144 + jp * 32 + vcol));
                mma_f16(oacc[2 * jp],     pfr[kk], v4);
                mma_f16(oacc[2 * jp + 1], pfr[kk], v4 + 2);
            }
            uint32_t v1[4];
            ldsm_x4_t(v1, sV + (uint32_t)((kk * 16 + l15) * 144 + 128));
            mma_f16(oaccl, pfr[kk], v1);
        }

        st = (st + 1) & 3;
    }

    // ---- epilogue: l from ones column; write O single fp16 plane ----
    int src = lane & ~3;
    float l0 = __shfl_sync(0xffffffffu, oaccl[0], src);
    float l1 = __shfl_sync(0xffffffffu, oaccl[2], src);
    float inv0 = 1.0f / l0;
    float inv1 = 1.0f / l1;
    int q0 = qt * 128 + wr0 + rg;
#pragma unroll
    for (int j = 0; j < 8; j++) {
        int cu = h * 32 + j * 4 + tg;
        g_Of[(size_t)(b * T_ + q0) * 512 + cu] =
            cvtf16x2(oacc[j][1] * inv0, oacc[j][0] * inv0);
        g_Of[(size_t)(b * T_ + q0 + 8) * 512 + cu] =
            cvtf16x2(oacc[j][3] * inv1, oacc[j][2] * inv1);
    }
}

// ---------------- launch ----------------
extern "C" void kernel_launch(void* const* d_in, const int* in_sizes, int n_in,
                              void* d_out, int out_size)
{
    const float* x    = (const float*)d_in[0];
    const int*   ids  = (const int*)d_in[1];
    const float* Wqkv = (const float*)d_in[2];
    const float* bqkv = (const float*)d_in[3];
    const float* Wout = (const float*)d_in[4];
    const float* bout = (const float*)d_in[5];
    float* out = (float*)d_out;

    uint32_t *xf, *wqf, *wof, *of;
    cudaGetSymbolAddress((void**)&xf, g_xf);
    cudaGetSymbolAddress((void**)&wqf, g_Wqf);
    cudaGetSymbolAddress((void**)&wof, g_Wof);
    cudaGetSymbolAddress((void**)&of, g_Of);

    cudaFuncSetAttribute(tc_gemm_f16<1>, cudaFuncAttributeMaxDynamicSharedMemorySize, 67584);
    cudaFuncSetAttribute(tc_gemm_f16<0>, cudaFuncAttributeMaxDynamicSharedMemorySize, 4 * GP_STAGE);
    cudaFuncSetAttribute(attn_kernel, cudaFuncAttributeMaxDynamicSharedMemorySize, AT_SMEM);

    // 0) fused conversions + rope table
    conv_fused<<<(NX + NWQ + NWO + NTAB + 255) / 256, 256>>>(
        (const float4*)x, (const float4*)Wqkv, (const float4*)Wout);

    // 1) QKV projection (single x single) with fused rope epilogue
    {
        dim3 grid(3 * D_ / 128, (B_ * T_) / 128);
        tc_gemm_f16<1><<<grid, 256, 67584>>>(xf, wqf, bqkv, nullptr,
                                             B_ * T_, 3 * D_, D_);
    }

    // 2) attention
    {
        dim3 grid(T_ / 128, H_, B_);
        attn_kernel<<<grid, 256, AT_SMEM>>>(ids);
    }

    // 3) output projection (single x single)
    {
        dim3 grid(D_ / 128, (B_ * T_) / 128);
        tc_gemm_f16<0><<<grid, 256, 4 * GP_STAGE>>>(of, wof, bout, out,
                                                    B_ * T_, D_, D_);
    }
}